// round 1
// baseline (speedup 1.0000x reference)
#include <cuda_runtime.h>
#include <cuda_bf16.h>

// Problem constants (fixed by the dataset)
#define MAX_ATOMS 8000
#define NF 32              // nf_in == nf_out
#define NDIST 16
#define NCOMP 4
#define FWCOLS (NDIST * NF)       // 512
#define BIGN (FWCOLS + NF)        // 544 (fw cols + self-interaction cols)
#define GN_EPS 1e-5f
#define HARD_CUTOFF 6.5f
// 0.5 * pi / 6.5
#define CUT_K 0.24166097335306083f

// Scratch: projected features fw[j][d][o] = sum_i feat[j,i] * W_int[d,o,i]
__device__ float d_fw[MAX_ATOMS * FWCOLS];

// ---------------------------------------------------------------------------
// K1: fused GEMM  C(8000 x 544) = feat(8000 x 32) @ Wbig(32 x 544)
//   cols [0,512): fw  (Wbig[i, d*32+o] = int_weights[d,o,i])
//   cols [512,544): self_part written directly to d_out (+ bias)
// Tile 64x64, 256 threads, 4x4 micro-tile, K=32 fully in shared.
// ---------------------------------------------------------------------------
__global__ __launch_bounds__(256) void k1_gemm(
    const float* __restrict__ feat,
    const float* __restrict__ intw,    // (16,32,32)
    const float* __restrict__ selfw,   // (32,32)
    const float* __restrict__ selfb,   // (32,)
    float* __restrict__ out,           // (N,32) gets self_part
    int n_atoms)
{
    __shared__ float sA[64][33];   // feat tile
    __shared__ float sB[32][65];   // weight tile

    const int tx = threadIdx.x & 15;
    const int ty = threadIdx.x >> 4;
    const int r0 = blockIdx.x * 64;
    const int c0 = blockIdx.y * 64;

    // load A tile (64 rows x 32 k)
    for (int idx = threadIdx.x; idx < 64 * 32; idx += 256) {
        int r = idx >> 5, c = idx & 31;
        int gr = r0 + r;
        sA[r][c] = (gr < n_atoms) ? feat[gr * NF + c] : 0.0f;
    }
    // load B tile (32 k x 64 cols) with on-the-fly weight transpose
    for (int idx = threadIdx.x; idx < 32 * 64; idx += 256) {
        int k = idx >> 6, c = idx & 63;
        int gc = c0 + c;
        float v = 0.0f;
        if (gc < FWCOLS) {
            int d = gc >> 5, o = gc & 31;
            v = intw[d * (NF * NF) + o * NF + k];
        } else if (gc < BIGN) {
            v = selfw[(gc - FWCOLS) * NF + k];
        }
        sB[k][c] = v;
    }
    __syncthreads();

    float acc[4][4];
#pragma unroll
    for (int i = 0; i < 4; i++)
#pragma unroll
        for (int j = 0; j < 4; j++) acc[i][j] = 0.0f;

#pragma unroll
    for (int k = 0; k < 32; k++) {
        float a[4], b[4];
#pragma unroll
        for (int i = 0; i < 4; i++) a[i] = sA[ty + 16 * i][k];
#pragma unroll
        for (int j = 0; j < 4; j++) b[j] = sB[k][tx + 16 * j];
#pragma unroll
        for (int i = 0; i < 4; i++)
#pragma unroll
            for (int j = 0; j < 4; j++) acc[i][j] += a[i] * b[j];
    }

#pragma unroll
    for (int i = 0; i < 4; i++) {
        int gr = r0 + ty + 16 * i;
        if (gr >= n_atoms) continue;
#pragma unroll
        for (int j = 0; j < 4; j++) {
            int gc = c0 + tx + 16 * j;
            if (gc < FWCOLS) {
                d_fw[gr * FWCOLS + gc] = acc[i][j];
            } else if (gc < BIGN) {
                int o = gc - FWCOLS;
                out[gr * NF + o] = acc[i][j] + selfb[o];
            }
        }
    }
}

// ---------------------------------------------------------------------------
// K2: fused pair-sum + invariants + GroupNorm + mixing. One warp per atom.
// pair_first is sorted -> binary search segment, register accumulation.
// ---------------------------------------------------------------------------
#define K2_WARPS 8

__device__ __forceinline__ float warpsum(float v) {
#pragma unroll
    for (int o = 16; o > 0; o >>= 1) v += __shfl_xor_sync(0xffffffffu, v, o);
    return v;
}

__global__ __launch_bounds__(K2_WARPS * 32) void k2_atom(
    const float* __restrict__ rhats,   // (P,4)
    const float* __restrict__ dist,    // (P,)
    const float* __restrict__ mu,      // (16,)
    const float* __restrict__ sigma,   // (16,)
    const int*   __restrict__ pf,      // (P,) sorted
    const int*   __restrict__ ps,      // (P,)
    const float* __restrict__ mixw,    // (32,2,32) -> flat (64,32)
    const float* __restrict__ gnw,     // (64,)
    const float* __restrict__ gnb,     // (64,)
    float* __restrict__ out,           // (N,32), already holds self_part
    int n_atoms, int n_pairs)
{
    __shared__ float sh_mix[64 * 32];
    __shared__ float sh_norm[K2_WARPS][64];

    for (int i = threadIdx.x; i < 64 * 32; i += K2_WARPS * 32)
        sh_mix[i] = mixw[i];
    __syncthreads();

    const int warp = threadIdx.x >> 5;
    const int lane = threadIdx.x & 31;
    const int a = blockIdx.x * K2_WARPS + warp;
    if (a >= n_atoms) return;

    // segment bounds: [p0, p1) = pairs with pair_first == a (uniform per warp)
    int p0, p1;
    {
        int lo = 0, hi = n_pairs;
        while (lo < hi) { int mid = (lo + hi) >> 1; if (pf[mid] < a) lo = mid + 1; else hi = mid; }
        p0 = lo;
        hi = n_pairs;
        while (lo < hi) { int mid = (lo + hi) >> 1; if (pf[mid] < a + 1) lo = mid + 1; else hi = mid; }
        p1 = lo;
    }

    const float mu_l = mu[lane & 15];
    const float isg_l = 1.0f / sigma[lane & 15];

    float acc0 = 0.0f, acc1 = 0.0f, acc2 = 0.0f, acc3 = 0.0f;

    for (int p = p0; p < p1; p++) {
        const int   j = ps[p];
        const float d = dist[p];
        // sensitivity: lanes compute gaussian for d_index = lane&15 (duplicated 2x)
        float t = (1.0f / d - mu_l) * isg_l;
        float cutv = 0.0f;
        if (d < HARD_CUTOFF) {
            float cc = __cosf(CUT_K * d);
            cutv = cc * cc;
        }
        float s = __expf(-0.5f * t * t) * cutv;

        const float* fwj = d_fw + (size_t)j * FWCOLS + lane;
        float m = 0.0f;
#pragma unroll
        for (int dd = 0; dd < NDIST; dd++) {
            float sd = __shfl_sync(0xffffffffu, s, dd);
            m += sd * fwj[dd * NF];
        }
        float4 rh = *reinterpret_cast<const float4*>(rhats + (size_t)p * 4);
        acc0 += rh.x * m;
        acc1 += rh.y * m;
        acc2 += rh.z * m;
        acc3 += rh.w * m;
    }

    // invariants: [l=0 scalar, |l=1 vector|^2], lane = channel
    float inv0 = acc0;
    float inv1 = acc1 * acc1 + acc2 * acc2 + acc3 * acc3;

    // GroupNorm (2 groups of 32 channels), two-pass over registers
    float mean0 = warpsum(inv0) * (1.0f / 32.0f);
    float c0 = inv0 - mean0;
    float var0 = warpsum(c0 * c0) * (1.0f / 32.0f);
    float y0 = c0 * rsqrtf(var0 + GN_EPS) * gnw[lane] + gnb[lane];

    float mean1 = warpsum(inv1) * (1.0f / 32.0f);
    float c1 = inv1 - mean1;
    float var1 = warpsum(c1 * c1) * (1.0f / 32.0f);
    float y1 = c1 * rsqrtf(var1 + GN_EPS) * gnw[32 + lane] + gnb[32 + lane];

    // norm_inv layout: index k = channel*2 + group
    sh_norm[warp][lane * 2 + 0] = y0;
    sh_norm[warp][lane * 2 + 1] = y1;
    __syncwarp();

    // mixing: out[a, lane] += sum_k sh_norm[k] * mixw[k, lane]
    float o = 0.0f;
#pragma unroll
    for (int k = 0; k < 64; k++)
        o += sh_norm[warp][k] * sh_mix[k * 32 + lane];

    out[a * NF + lane] += o;   // self_part already there from K1
}

extern "C" void kernel_launch(void* const* d_in, const int* in_sizes, int n_in,
                              void* d_out, int out_size)
{
    const float* feat  = (const float*)d_in[0];   // in_features (N,32)
    const float* rhats = (const float*)d_in[1];   // tensor_rhats (P,4)
    const float* dist  = (const float*)d_in[2];   // dist_pairs (P,)
    const float* intw  = (const float*)d_in[3];   // int_weights (16,32,32)
    const float* selfw = (const float*)d_in[4];   // selfint_w (32,32)
    const float* selfb = (const float*)d_in[5];   // selfint_b (32,)
    const float* mixw  = (const float*)d_in[6];   // mixing_weights (32,2,32)
    const float* gnw   = (const float*)d_in[7];   // gn_weight (64,)
    const float* gnb   = (const float*)d_in[8];   // gn_bias (64,)
    const float* mu    = (const float*)d_in[9];   // sens_mu (16,)
    const float* sg    = (const float*)d_in[10];  // sens_sigma (16,)
    const int*   pf    = (const int*)d_in[11];    // pair_first (P,) sorted
    const int*   ps    = (const int*)d_in[12];    // pair_second (P,)
    float* out = (float*)d_out;

    const int n_atoms = in_sizes[0] / NF;
    const int n_pairs = in_sizes[2];

    dim3 g1((n_atoms + 63) / 64, (BIGN + 63) / 64);
    k1_gemm<<<g1, 256>>>(feat, intw, selfw, selfb, out, n_atoms);

    int blocks = (n_atoms + K2_WARPS - 1) / K2_WARPS;
    k2_atom<<<blocks, K2_WARPS * 32>>>(rhats, dist, mu, sg, pf, ps,
                                       mixw, gnw, gnb, out, n_atoms, n_pairs);
}